// round 1
// baseline (speedup 1.0000x reference)
#include <cuda_runtime.h>
#include <math.h>
#include <stdint.h>

#define NH   16
#define NKV  4
#define HD   128
#define HIDD 2048
#define FFI  8192
#define QKVW ((NH + 2*NKV) * HD)   /* 3072 */
#define NEGV -1e30f

// ---------------- scratch (B=4, S=1024 fixed by problem) ----------------
static __device__ float g_h[4096L * HIDD];
static __device__ float g_qkv[4096L * QKVW];
static __device__ float g_scores[(long)4 * NH * 1024 * 1024];
static __device__ float g_attnout[4096L * HIDD];
static __device__ float g_h1[4096L * HIDD];
static __device__ float g_gu[4096L * 2 * FFI];
static __device__ float g_act[4096L * FFI];

// ---------------- block reductions (256-thread 1D blocks) ----------------
__device__ __forceinline__ float block_sum(float v) {
    #pragma unroll
    for (int o = 16; o > 0; o >>= 1) v += __shfl_xor_sync(0xffffffffu, v, o);
    __shared__ float sh[8];
    __shared__ float total;
    int w = threadIdx.x >> 5, l = threadIdx.x & 31;
    if (l == 0) sh[w] = v;
    __syncthreads();
    if (threadIdx.x == 0) {
        float s = 0.f;
        #pragma unroll
        for (int i = 0; i < 8; i++) s += sh[i];
        total = s;
    }
    __syncthreads();
    return total;
}

__device__ __forceinline__ float block_max(float v) {
    #pragma unroll
    for (int o = 16; o > 0; o >>= 1) v = fmaxf(v, __shfl_xor_sync(0xffffffffu, v, o));
    __shared__ float shm[8];
    __shared__ float totalm;
    int w = threadIdx.x >> 5, l = threadIdx.x & 31;
    if (l == 0) shm[w] = v;
    __syncthreads();
    if (threadIdx.x == 0) {
        float s = -3.4e38f;
        #pragma unroll
        for (int i = 0; i < 8; i++) s = fmaxf(s, shm[i]);
        totalm = s;
    }
    __syncthreads();
    return totalm;
}

// ---------------- elementwise kernels ----------------
__global__ void rmsnorm_kernel(const float* __restrict__ x, const float* __restrict__ w,
                               float* __restrict__ out, int ncols) {
    long row = blockIdx.x;
    const float* xr = x + row * ncols;
    float s = 0.f;
    for (int i = threadIdx.x; i < ncols; i += 256) { float v = xr[i]; s += v * v; }
    s = block_sum(s);
    float inv = rsqrtf(s / (float)ncols + 1e-6f);
    float* o = out + row * ncols;
    for (int i = threadIdx.x; i < ncols; i += 256) o[i] = xr[i] * inv * w[i];
}

// q heads (0..NH-1) and k heads (NH..NH+NKV-1) are contiguous in qkv columns.
__global__ void rope_kernel(float* __restrict__ qkv, const int* __restrict__ pos, int S) {
    long bs = blockIdx.x;
    int head = blockIdx.y;
    int i = threadIdx.x;          // 0..63 (half of D)
    int s = (int)(bs % S);
    float* base = qkv + bs * QKVW + (long)head * HD;
    float inv = powf(10000.f, -(float)i / 64.f);
    float ang = (float)pos[s] * inv;
    float sn, cs;
    sincosf(ang, &sn, &cs);
    float t1 = base[i], t2 = base[i + 64];
    base[i]      = t1 * cs - t2 * sn;
    base[i + 64] = t2 * cs + t1 * sn;
}

__global__ void softmax_kernel(float* __restrict__ sc, int S) {
    float* p = sc + (long)blockIdx.x * S;
    float mx = -3.4e38f;
    for (int i = threadIdx.x; i < S; i += 256) mx = fmaxf(mx, p[i]);
    mx = block_max(mx);
    float sum = 0.f;
    for (int i = threadIdx.x; i < S; i += 256) {
        float e = __expf(p[i] - mx);
        p[i] = e;
        sum += e;
    }
    sum = block_sum(sum);
    float r = 1.f / sum;
    for (int i = threadIdx.x; i < S; i += 256) p[i] *= r;
}

__global__ void silu_kernel(const float* __restrict__ gu, float* __restrict__ act, long total) {
    long idx = (long)blockIdx.x * 256 + threadIdx.x;
    if (idx >= total) return;
    long row = idx / FFI;
    int  j   = (int)(idx - row * FFI);
    float g = gu[row * (2L * FFI) + j];
    float u = gu[row * (2L * FFI) + FFI + j];
    act[idx] = (g / (1.f + expf(-g))) * u;
}

// ---------------- generic 128x128x16 tiled GEMM ----------------
// C[m,n] = alpha * sum_k A[m,k] * (TRANSB ? B[n,k] : B[k,n])   (+ causal mask) (+ residual R)
// Strided batch: z = blockIdx.z over Hn heads per batch element:
//   offA = b*sAb + h*sAh ; offB = b*sBb + (h/divB)*sBh ; offC = b*sCb + h*sCh
template<bool TRANSB, bool CAUSAL, bool RES>
__global__ void __launch_bounds__(256, 2)
gemm128(const float* __restrict__ A, const float* __restrict__ B,
        const float* __restrict__ R, float* __restrict__ C,
        int M, int N, int K, int lda, int ldb, int ldc,
        int Hn, int divB,
        long sAb, long sAh, long sBb, long sBh, long sCb, long sCh,
        float alpha)
{
    const int m0 = blockIdx.y * 128, n0 = blockIdx.x * 128;
    long offA = 0, offB = 0, offC = 0;
    if (Hn > 0) {
        int z = blockIdx.z;
        int b = z / Hn, h = z - b * Hn;
        offA = b * sAb + (long)h * sAh;
        offB = b * sBb + (long)(h / divB) * sBh;
        offC = b * sCb + (long)h * sCh;
    }
    const int tx = threadIdx.x, ty = threadIdx.y;
    const int tid = ty * 16 + tx;

    if (CAUSAL && n0 >= m0 + 128) {
        // fully masked tile: write NEG and bail
        #pragma unroll
        for (int i = 0; i < 8; i++) {
            long row = m0 + ty * 8 + i;
            #pragma unroll
            for (int j = 0; j < 8; j++)
                C[offC + row * ldc + n0 + tx * 8 + j] = NEGV;
        }
        return;
    }

    __shared__ float As[16][132];
    __shared__ float Bs[16][132];

    float acc[8][8];
    #pragma unroll
    for (int i = 0; i < 8; i++)
        #pragma unroll
        for (int j = 0; j < 8; j++) acc[i][j] = 0.f;

    const int ra = tid >> 2;            // 0..63
    const int ca = (tid & 3) * 4;       // 0,4,8,12
    const int rb = tid >> 5;            // 0..7
    const int cb4 = (tid & 31) * 4;     // 0..124

    for (int k0 = 0; k0 < K; k0 += 16) {
        // A tile (128x16) -> As[k][m]
        float4 a0 = *(const float4*)&A[offA + (long)(m0 + ra) * lda + k0 + ca];
        float4 a1 = *(const float4*)&A[offA + (long)(m0 + ra + 64) * lda + k0 + ca];
        As[ca + 0][ra] = a0.x; As[ca + 1][ra] = a0.y; As[ca + 2][ra] = a0.z; As[ca + 3][ra] = a0.w;
        As[ca + 0][ra + 64] = a1.x; As[ca + 1][ra + 64] = a1.y; As[ca + 2][ra + 64] = a1.z; As[ca + 3][ra + 64] = a1.w;

        if (TRANSB) {
            // B is (N x K): tile 128 rows x 16 cols -> Bs[k][n]
            float4 b0 = *(const float4*)&B[offB + (long)(n0 + ra) * ldb + k0 + ca];
            float4 b1 = *(const float4*)&B[offB + (long)(n0 + ra + 64) * ldb + k0 + ca];
            Bs[ca + 0][ra] = b0.x; Bs[ca + 1][ra] = b0.y; Bs[ca + 2][ra] = b0.z; Bs[ca + 3][ra] = b0.w;
            Bs[ca + 0][ra + 64] = b1.x; Bs[ca + 1][ra + 64] = b1.y; Bs[ca + 2][ra + 64] = b1.z; Bs[ca + 3][ra + 64] = b1.w;
        } else {
            // B is (K x N): tile 16 rows x 128 cols
            float4 b0 = *(const float4*)&B[offB + (long)(k0 + rb) * ldb + n0 + cb4];
            float4 b1 = *(const float4*)&B[offB + (long)(k0 + rb + 8) * ldb + n0 + cb4];
            *(float4*)&Bs[rb][cb4] = b0;
            *(float4*)&Bs[rb + 8][cb4] = b1;
        }
        __syncthreads();

        #pragma unroll
        for (int kk = 0; kk < 16; kk++) {
            float a[8], b[8];
            *(float4*)&a[0] = *(const float4*)&As[kk][ty * 8];
            *(float4*)&a[4] = *(const float4*)&As[kk][ty * 8 + 4];
            *(float4*)&b[0] = *(const float4*)&Bs[kk][tx * 8];
            *(float4*)&b[4] = *(const float4*)&Bs[kk][tx * 8 + 4];
            #pragma unroll
            for (int i = 0; i < 8; i++)
                #pragma unroll
                for (int j = 0; j < 8; j++)
                    acc[i][j] = fmaf(a[i], b[j], acc[i][j]);
        }
        __syncthreads();
    }

    #pragma unroll
    for (int i = 0; i < 8; i++) {
        long row = m0 + ty * 8 + i;
        #pragma unroll
        for (int j = 0; j < 8; j++) {
            long col = n0 + tx * 8 + j;
            float v = acc[i][j] * alpha;
            if (CAUSAL && col > row) v = NEGV;
            if (RES) v += R[offC + row * ldc + col];
            C[offC + row * ldc + col] = v;
        }
    }
}

// ---------------- host launcher ----------------
extern "C" void kernel_launch(void* const* d_in, const int* in_sizes, int n_in,
                              void* d_out, int out_size) {
    const float* x         = (const float*)d_in[0];
    const float* ln1_w     = (const float*)d_in[1];
    const float* wqkv      = (const float*)d_in[2];
    const float* wo        = (const float*)d_in[3];
    const float* ln2_w     = (const float*)d_in[4];
    const float* w_gate_up = (const float*)d_in[5];
    const float* w_down    = (const float*)d_in[6];
    const int*   pos       = (const int*)d_in[7];
    float* out = (float*)d_out;

    const int S  = in_sizes[7];                 // 1024
    const long BS = (long)in_sizes[0] / HIDD;   // B*S = 4096
    const int Bb = (int)(BS / S);               // 4

    float *pH, *pQKV, *pSC, *pAO, *pH1, *pGU, *pACT;
    cudaGetSymbolAddress((void**)&pH,   g_h);
    cudaGetSymbolAddress((void**)&pQKV, g_qkv);
    cudaGetSymbolAddress((void**)&pSC,  g_scores);
    cudaGetSymbolAddress((void**)&pAO,  g_attnout);
    cudaGetSymbolAddress((void**)&pH1,  g_h1);
    cudaGetSymbolAddress((void**)&pGU,  g_gu);
    cudaGetSymbolAddress((void**)&pACT, g_act);

    dim3 blk(16, 16);
    const float inv_sqrt_d = 0.08838834764831843f;   // 1/sqrt(128)

    // 1. h = rmsnorm(x, ln1_w)
    rmsnorm_kernel<<<(int)BS, 256>>>(x, ln1_w, pH, HIDD);

    // 2. qkv = h @ wqkv   [BS x 3072]
    gemm128<false, false, false><<<dim3(QKVW / 128, (int)(BS / 128), 1), blk>>>(
        pH, wqkv, nullptr, pQKV, (int)BS, QKVW, HIDD, HIDD, QKVW, QKVW,
        0, 1, 0, 0, 0, 0, 0, 0, 1.f);

    // 3. rope on q (16 heads) and k (4 heads, contiguous after q)
    rope_kernel<<<dim3((unsigned)BS, NH + NKV), 64>>>(pQKV, pos, S);

    // 4. scores = (Q @ K^T) / sqrt(D), causal-masked.  batch z = (b, h)
    gemm128<true, true, false><<<dim3(S / 128, S / 128, Bb * NH), blk>>>(
        pQKV, pQKV + NH * HD, nullptr, pSC,
        S, S, HD, QKVW, QKVW, S,
        NH, NH / NKV,
        (long)S * QKVW, HD,           // A: b, h
        (long)S * QKVW, HD,           // B: b, h/4
        (long)NH * S * S, (long)S * S,
        inv_sqrt_d);

    // 5. softmax rows
    softmax_kernel<<<(unsigned)(Bb * NH * S), 256>>>(pSC, S);

    // 6. O = P @ V  -> attnout laid out [b, s, h, d]
    gemm128<false, false, false><<<dim3(HD / 128, S / 128, Bb * NH), blk>>>(
        pSC, pQKV + (NH + NKV) * HD, nullptr, pAO,
        S, HD, S, S, QKVW, HIDD,
        NH, NH / NKV,
        (long)NH * S * S, (long)S * S,
        (long)S * QKVW, HD,
        (long)S * HIDD, HD,
        1.f);

    // 7. h1 = x + attnout @ wo
    gemm128<false, false, true><<<dim3(HIDD / 128, (int)(BS / 128), 1), blk>>>(
        pAO, wo, x, pH1, (int)BS, HIDD, HIDD, HIDD, HIDD, HIDD,
        0, 1, 0, 0, 0, 0, 0, 0, 1.f);

    // 8. h2 = rmsnorm(h1, ln2_w)  (reuse g_h)
    rmsnorm_kernel<<<(int)BS, 256>>>(pH1, ln2_w, pH, HIDD);

    // 9. gu = h2 @ w_gate_up   [BS x 16384]
    gemm128<false, false, false><<<dim3(2 * FFI / 128, (int)(BS / 128), 1), blk>>>(
        pH, w_gate_up, nullptr, pGU, (int)BS, 2 * FFI, HIDD, HIDD, 2 * FFI, 2 * FFI,
        0, 1, 0, 0, 0, 0, 0, 0, 1.f);

    // 10. act = silu(gate) * up
    long total = BS * FFI;
    silu_kernel<<<(unsigned)((total + 255) / 256), 256>>>(pGU, pACT, total);

    // 11. out = h1 + act @ w_down
    gemm128<false, false, true><<<dim3(HIDD / 128, (int)(BS / 128), 1), blk>>>(
        pACT, w_down, pH1, out, (int)BS, HIDD, FFI, FFI, HIDD, HIDD,
        0, 1, 0, 0, 0, 0, 0, 0, 1.f);
}

// round 3
// speedup vs baseline: 2.2622x; 2.2622x over previous
#include <cuda_runtime.h>
#include <cuda_bf16.h>
#include <math.h>
#include <stdint.h>

#define NH   16
#define NKV  4
#define HD   128
#define HIDD 2048
#define FFI  8192
#define QKVW ((NH + 2*NKV) * HD)   /* 3072 */
#define NEGV -1e30f

// ================= scratch (B=4, S=1024) =================
static __device__ float g_qkv[4096L * QKVW];
static __device__ float g_scores[(long)4 * NH * 1024 * 1024];
static __device__ float g_attnout[4096L * HIDD];
static __device__ float g_h1[4096L * HIDD];
static __device__ float g_gu[4096L * 2 * FFI];

static __device__ __nv_bfloat16 g_hh[4096L * HIDD],  g_hl[4096L * HIDD];
static __device__ __nv_bfloat16 g_aoh[4096L * HIDD], g_aol[4096L * HIDD];
static __device__ __nv_bfloat16 g_acth[4096L * FFI], g_actl[4096L * FFI];
static __device__ __nv_bfloat16 g_wqkvTh[(long)QKVW * HIDD], g_wqkvTl[(long)QKVW * HIDD];
static __device__ __nv_bfloat16 g_woTh[(long)HIDD * HIDD],   g_woTl[(long)HIDD * HIDD];
static __device__ __nv_bfloat16 g_guTh[(long)2*FFI * HIDD],  g_guTl[(long)2*FFI * HIDD];
static __device__ __nv_bfloat16 g_dnTh[(long)HIDD * FFI],    g_dnTl[(long)HIDD * FFI];

// ================= PTX helpers =================
__device__ __forceinline__ uint32_t smem_u32(const void* p) {
    uint32_t a;
    asm("{ .reg .u64 t; cvta.to.shared.u64 t, %1; cvt.u32.u64 %0, t; }" : "=r"(a) : "l"(p));
    return a;
}
__device__ __forceinline__ void cp16(uint32_t dst, const void* src) {
    asm volatile("cp.async.cg.shared.global [%0], [%1], 16;" :: "r"(dst), "l"(src));
}
__device__ __forceinline__ void cp_commit() { asm volatile("cp.async.commit_group;"); }
__device__ __forceinline__ void cp_wait1() { asm volatile("cp.async.wait_group 1;"); }
__device__ __forceinline__ void cp_wait0() { asm volatile("cp.async.wait_group 0;"); }

__device__ __forceinline__ void ldm_x4(uint32_t* r, uint32_t addr) {
    asm volatile("ldmatrix.sync.aligned.m8n8.x4.shared.b16 {%0,%1,%2,%3}, [%4];"
        : "=r"(r[0]), "=r"(r[1]), "=r"(r[2]), "=r"(r[3]) : "r"(addr));
}
__device__ __forceinline__ void mma16816(float* d, const uint32_t* a, const uint32_t* b) {
    asm volatile("mma.sync.aligned.m16n8k16.row.col.f32.bf16.bf16.f32 "
        "{%0,%1,%2,%3}, {%4,%5,%6,%7}, {%8,%9}, {%0,%1,%2,%3};"
        : "+f"(d[0]), "+f"(d[1]), "+f"(d[2]), "+f"(d[3])
        : "r"(a[0]), "r"(a[1]), "r"(a[2]), "r"(a[3]), "r"(b[0]), "r"(b[1]));
}

// ================= HMMA TN GEMM (bf16x3, fp32 accum) =================
// C[M,N] = Ahi/lo[M,K] x (Bhi/lo[N,K])^T  (+ residual R).
// CTA tile 128x128, BK=64, 8 warps (2x4), warp tile 64x32.
#define SAS 72                               /* smem row stride in bf16 elems */
#define TILEB (128 * SAS * 2)                /* 18432 B per tile */
#define STAGE (4 * TILEB)                    /* Ahi Alo Bhi Blo */
#define HG_SMEM (2 * STAGE)                  /* 147456 B */

template<bool RES>
__global__ void __launch_bounds__(256, 1)
hgemm(const __nv_bfloat16* __restrict__ Ahi, const __nv_bfloat16* __restrict__ Alo,
      const __nv_bfloat16* __restrict__ Bhi, const __nv_bfloat16* __restrict__ Blo,
      const float* __restrict__ R, float* __restrict__ C, int K, int N)
{
    extern __shared__ char sm[];
    const uint32_t sbase = smem_u32(sm);
    const int tid = threadIdx.x;
    const int m0 = blockIdx.x * 128, n0 = blockIdx.y * 128;
    const int wid = tid >> 5, lane = tid & 31;
    const int wm = (wid >> 2) * 64;     // warp row offset (0 / 64)
    const int wn = (wid & 3) * 32;      // warp col offset (0/32/64/96)

    const __nv_bfloat16* srcs[4] = {
        Ahi + (long)m0 * K, Alo + (long)m0 * K,
        Bhi + (long)n0 * K, Blo + (long)n0 * K };

    // ldmatrix per-thread address components
    const int alr = lane & 15, alc = (lane >> 4) * 8;          // A: rows m, col half
    const int blr = lane & 7;
    const int bhalf = (lane >> 3) & 1;                          // k half (0/8)
    const int bquad = (lane >> 4) * 8;                          // n half (0/8)

    float acc[4][4][4];
    #pragma unroll
    for (int i = 0; i < 4; i++)
        #pragma unroll
        for (int j = 0; j < 4; j++)
            #pragma unroll
            for (int q = 0; q < 4; q++) acc[i][j][q] = 0.f;

    const int NB = K >> 6;

    auto load_stage = [&](int s, int blk) {
        const long kb = (long)blk << 6;
        #pragma unroll
        for (int t = 0; t < 4; t++) {
            const __nv_bfloat16* S = srcs[t] + kb;
            const uint32_t dbase = sbase + s * STAGE + t * TILEB;
            #pragma unroll
            for (int i = 0; i < 4; i++) {
                int idx = tid + 256 * i;
                int r = idx >> 3, c = idx & 7;
                cp16(dbase + (r * SAS + c * 8) * 2, S + (long)r * K + c * 8);
            }
        }
        cp_commit();
    };

    load_stage(0, 0);

    for (int blk = 0; blk < NB; blk++) {
        const int s = blk & 1;
        if (blk + 1 < NB) { load_stage(s ^ 1, blk + 1); cp_wait1(); }
        else              { cp_wait0(); }
        __syncthreads();

        const uint32_t sAh = sbase + s * STAGE;
        const uint32_t sAl = sAh + TILEB;
        const uint32_t sBh = sAh + 2 * TILEB;
        const uint32_t sBl = sAh + 3 * TILEB;

        #pragma unroll
        for (int kt = 0; kt < 4; kt++) {
            uint32_t ah[4][4], al[4][4], bh[4][2], bl[4][2];
            #pragma unroll
            for (int ma = 0; ma < 4; ma++) {
                uint32_t ao = ((wm + ma * 16 + alr) * SAS + kt * 16 + alc) * 2;
                ldm_x4(ah[ma], sAh + ao);
                ldm_x4(al[ma], sAl + ao);
            }
            #pragma unroll
            for (int np = 0; np < 2; np++) {
                uint32_t bo = ((wn + np * 16 + bquad + blr) * SAS + kt * 16 + bhalf * 8) * 2;
                uint32_t t4[4];
                ldm_x4(t4, sBh + bo);
                bh[np*2+0][0] = t4[0]; bh[np*2+0][1] = t4[1];
                bh[np*2+1][0] = t4[2]; bh[np*2+1][1] = t4[3];
                ldm_x4(t4, sBl + bo);
                bl[np*2+0][0] = t4[0]; bl[np*2+0][1] = t4[1];
                bl[np*2+1][0] = t4[2]; bl[np*2+1][1] = t4[3];
            }
            #pragma unroll
            for (int ma = 0; ma < 4; ma++)
                #pragma unroll
                for (int na = 0; na < 4; na++) {
                    mma16816(acc[ma][na], ah[ma], bh[na]);
                    mma16816(acc[ma][na], ah[ma], bl[na]);
                    mma16816(acc[ma][na], al[ma], bh[na]);
                }
        }
        __syncthreads();
    }

    // epilogue
    const int erow = lane >> 2, ecol = (lane & 3) * 2;
    #pragma unroll
    for (int ma = 0; ma < 4; ma++) {
        #pragma unroll
        for (int na = 0; na < 4; na++) {
            long r0 = m0 + wm + ma * 16 + erow;
            long cc = n0 + wn + na * 8 + ecol;
            float2 v0 = { acc[ma][na][0], acc[ma][na][1] };
            float2 v1 = { acc[ma][na][2], acc[ma][na][3] };
            if (RES) {
                const float2 q0 = *(const float2*)&R[r0 * N + cc];
                const float2 q1 = *(const float2*)&R[(r0 + 8) * N + cc];
                v0.x += q0.x; v0.y += q0.y;
                v1.x += q1.x; v1.y += q1.y;
            }
            *(float2*)&C[r0 * N + cc] = v0;
            *(float2*)&C[(r0 + 8) * N + cc] = v1;
        }
    }
}

// ================= block reductions =================
__device__ __forceinline__ float block_sum(float v) {
    #pragma unroll
    for (int o = 16; o > 0; o >>= 1) v += __shfl_xor_sync(0xffffffffu, v, o);
    __shared__ float sh[8]; __shared__ float total;
    int w = threadIdx.x >> 5, l = threadIdx.x & 31;
    if (l == 0) sh[w] = v;
    __syncthreads();
    if (threadIdx.x == 0) { float s = 0.f; for (int i = 0; i < 8; i++) s += sh[i]; total = s; }
    __syncthreads();
    return total;
}
__device__ __forceinline__ float block_max(float v) {
    #pragma unroll
    for (int o = 16; o > 0; o >>= 1) v = fmaxf(v, __shfl_xor_sync(0xffffffffu, v, o));
    __shared__ float shm[8]; __shared__ float totalm;
    int w = threadIdx.x >> 5, l = threadIdx.x & 31;
    if (l == 0) shm[w] = v;
    __syncthreads();
    if (threadIdx.x == 0) { float s = -3.4e38f; for (int i = 0; i < 8; i++) s = fmaxf(s, shm[i]); totalm = s; }
    __syncthreads();
    return totalm;
}

// ================= elementwise =================
__device__ __forceinline__ void split_store(float v, __nv_bfloat16* hi, __nv_bfloat16* lo, long idx) {
    __nv_bfloat16 h = __float2bfloat16(v);
    hi[idx] = h;
    lo[idx] = __float2bfloat16(v - __bfloat162float(h));
}

__global__ void rmsnorm_bf16_kernel(const float* __restrict__ x, const float* __restrict__ w,
                                    __nv_bfloat16* __restrict__ hi, __nv_bfloat16* __restrict__ lo) {
    long row = blockIdx.x;
    const float* xr = x + row * HIDD;
    float s = 0.f;
    for (int i = threadIdx.x; i < HIDD; i += 256) { float v = xr[i]; s += v * v; }
    s = block_sum(s);
    float inv = rsqrtf(s / (float)HIDD + 1e-6f);
    for (int i = threadIdx.x; i < HIDD; i += 256)
        split_store(xr[i] * inv * w[i], hi, lo, row * HIDD + i);
}

__global__ void conv_hilo_kernel(const float* __restrict__ in,
                                 __nv_bfloat16* __restrict__ hi, __nv_bfloat16* __restrict__ lo, long n) {
    long idx = (long)blockIdx.x * 256 + threadIdx.x;
    if (idx < n) split_store(in[idx], hi, lo, idx);
}

__global__ void silu_bf16_kernel(const float* __restrict__ gu,
                                 __nv_bfloat16* __restrict__ hi, __nv_bfloat16* __restrict__ lo, long total) {
    long idx = (long)blockIdx.x * 256 + threadIdx.x;
    if (idx >= total) return;
    long row = idx / FFI;
    int  j   = (int)(idx - row * FFI);
    float g = gu[row * (2L * FFI) + j];
    float u = gu[row * (2L * FFI) + FFI + j];
    split_store((g / (1.f + expf(-g))) * u, hi, lo, idx);
}

// transpose-convert: W [K,N] fp32 -> T [N,K] bf16 hi/lo
__global__ void convT_kernel(const float* __restrict__ W,
                             __nv_bfloat16* __restrict__ Thi, __nv_bfloat16* __restrict__ Tlo,
                             int K, int N) {
    __shared__ float t[32][33];
    int n0 = blockIdx.x * 32, k0 = blockIdx.y * 32;
    for (int i = threadIdx.y; i < 32; i += 8)
        t[i][threadIdx.x] = W[(long)(k0 + i) * N + n0 + threadIdx.x];
    __syncthreads();
    for (int i = threadIdx.y; i < 32; i += 8) {
        float v = t[threadIdx.x][i];   // = W[k0+tx][n0+i]
        long o = (long)(n0 + i) * K + k0 + threadIdx.x;
        __nv_bfloat16 h = __float2bfloat16(v);
        Thi[o] = h;
        Tlo[o] = __float2bfloat16(v - __bfloat162float(h));
    }
}

__global__ void rope_kernel(float* __restrict__ qkv, const int* __restrict__ pos, int S) {
    long bs = blockIdx.x;
    int head = blockIdx.y;
    int i = threadIdx.x;
    int s = (int)(bs % S);
    float* base = qkv + bs * QKVW + (long)head * HD;
    float inv = powf(10000.f, -(float)i / 64.f);
    float ang = (float)pos[s] * inv;
    float sn, cs;
    sincosf(ang, &sn, &cs);
    float t1 = base[i], t2 = base[i + 64];
    base[i]      = t1 * cs - t2 * sn;
    base[i + 64] = t2 * cs + t1 * sn;
}

__global__ void softmax_kernel(float* __restrict__ sc, int S) {
    float* p = sc + (long)blockIdx.x * S;
    float mx = -3.4e38f;
    for (int i = threadIdx.x; i < S; i += 256) mx = fmaxf(mx, p[i]);
    mx = block_max(mx);
    float sum = 0.f;
    for (int i = threadIdx.x; i < S; i += 256) {
        float e = __expf(p[i] - mx);
        p[i] = e;
        sum += e;
    }
    sum = block_sum(sum);
    float r = 1.f / sum;
    for (int i = threadIdx.x; i < S; i += 256) p[i] *= r;
}

// ================= SIMT GEMM for attention (verified R1) =================
template<bool TRANSB, bool CAUSAL>
__global__ void __launch_bounds__(256, 2)
gemm128(const float* __restrict__ A, const float* __restrict__ B, float* __restrict__ C,
        int M, int N, int K, int lda, int ldb, int ldc,
        int Hn, int divB,
        long sAb, long sAh, long sBb, long sBh, long sCb, long sCh,
        float alpha)
{
    const int m0 = blockIdx.y * 128, n0 = blockIdx.x * 128;
    long offA = 0, offB = 0, offC = 0;
    {
        int z = blockIdx.z;
        int b = z / Hn, h = z - b * Hn;
        offA = b * sAb + (long)h * sAh;
        offB = b * sBb + (long)(h / divB) * sBh;
        offC = b * sCb + (long)h * sCh;
    }
    const int tx = threadIdx.x, ty = threadIdx.y;
    const int tid = ty * 16 + tx;

    if (CAUSAL && n0 >= m0 + 128) {
        #pragma unroll
        for (int i = 0; i < 8; i++) {
            long row = m0 + ty * 8 + i;
            #pragma unroll
            for (int j = 0; j < 8; j++)
                C[offC + row * ldc + n0 + tx * 8 + j] = NEGV;
        }
        return;
    }

    __shared__ float As[16][132];
    __shared__ float Bs[16][132];
    float acc[8][8];
    #pragma unroll
    for (int i = 0; i < 8; i++)
        #pragma unroll
        for (int j = 0; j < 8; j++) acc[i][j] = 0.f;

    const int ra = tid >> 2;
    const int ca = (tid & 3) * 4;
    const int rb = tid >> 5;
    const int cb4 = (tid & 31) * 4;

    for (int k0 = 0; k0 < K; k0 += 16) {
        float4 a0 = *(const float4*)&A[offA + (long)(m0 + ra) * lda + k0 + ca];
        float4 a1 = *(const float4*)&A[offA + (long)(m0 + ra + 64) * lda + k0 + ca];
        As[ca+0][ra] = a0.x; As[ca+1][ra] = a0.y; As[ca+2][ra] = a0.z; As[ca+3][ra] = a0.w;
        As[ca+0][ra+64] = a1.x; As[ca+1][ra+64] = a1.y; As[ca+2][ra+64] = a1.z; As[ca+3][ra+64] = a1.w;
        if (TRANSB) {
            float4 b0 = *(const float4*)&B[offB + (long)(n0 + ra) * ldb + k0 + ca];
            float4 b1 = *(const float4*)&B[offB + (long)(n0 + ra + 64) * ldb + k0 + ca];
            Bs[ca+0][ra] = b0.x; Bs[ca+1][ra] = b0.y; Bs[ca+2][ra] = b0.z; Bs[ca+3][ra] = b0.w;
            Bs[ca+0][ra+64] = b1.x; Bs[ca+1][ra+64] = b1.y; Bs[ca+2][ra+64] = b1.z; Bs[ca+3][ra+64] = b1.w;
        } else {
            float4 b0 = *(const float4*)&B[offB + (long)(k0 + rb) * ldb + n0 + cb4];
            float4 b1 = *(const float4*)&B[offB + (long)(k0 + rb + 8) * ldb + n0 + cb4];
            *(float4*)&Bs[rb][cb4] = b0;
            *(float4*)&Bs[rb + 8][cb4] = b1;
        }
        __syncthreads();
        #pragma unroll
        for (int kk = 0; kk < 16; kk++) {
            float a[8], b[8];
            *(float4*)&a[0] = *(const float4*)&As[kk][ty * 8];
            *(float4*)&a[4] = *(const float4*)&As[kk][ty * 8 + 4];
            *(float4*)&b[0] = *(const float4*)&Bs[kk][tx * 8];
            *(float4*)&b[4] = *(const float4*)&Bs[kk][tx * 8 + 4];
            #pragma unroll
            for (int i = 0; i < 8; i++)
                #pragma unroll
                for (int j = 0; j < 8; j++)
                    acc[i][j] = fmaf(a[i], b[j], acc[i][j]);
        }
        __syncthreads();
    }
    #pragma unroll
    for (int i = 0; i < 8; i++) {
        long row = m0 + ty * 8 + i;
        #pragma unroll
        for (int j = 0; j < 8; j++) {
            long col = n0 + tx * 8 + j;
            float v = acc[i][j] * alpha;
            if (CAUSAL && col > row) v = NEGV;
            C[offC + row * ldc + col] = v;
        }
    }
}

// ================= host launcher =================
extern "C" void kernel_launch(void* const* d_in, const int* in_sizes, int n_in,
                              void* d_out, int out_size) {
    const float* x         = (const float*)d_in[0];
    const float* ln1_w     = (const float*)d_in[1];
    const float* wqkv      = (const float*)d_in[2];
    const float* wo        = (const float*)d_in[3];
    const float* ln2_w     = (const float*)d_in[4];
    const float* w_gate_up = (const float*)d_in[5];
    const float* w_down    = (const float*)d_in[6];
    const int*   pos       = (const int*)d_in[7];
    float* out = (float*)d_out;

    const int S  = in_sizes[7];
    const long BS = (long)in_sizes[0] / HIDD;
    const int Bb = (int)(BS / S);

    float *pQKV, *pSC, *pAO, *pH1, *pGU;
    cudaGetSymbolAddress((void**)&pQKV, g_qkv);
    cudaGetSymbolAddress((void**)&pSC,  g_scores);
    cudaGetSymbolAddress((void**)&pAO,  g_attnout);
    cudaGetSymbolAddress((void**)&pH1,  g_h1);
    cudaGetSymbolAddress((void**)&pGU,  g_gu);
    __nv_bfloat16 *pHh,*pHl,*pAOh,*pAOl,*pACTh,*pACTl;
    __nv_bfloat16 *pQKVTh,*pQKVTl,*pWOTh,*pWOTl,*pGUTh,*pGUTl,*pDNTh,*pDNTl;
    cudaGetSymbolAddress((void**)&pHh, g_hh);     cudaGetSymbolAddress((void**)&pHl, g_hl);
    cudaGetSymbolAddress((void**)&pAOh, g_aoh);   cudaGetSymbolAddress((void**)&pAOl, g_aol);
    cudaGetSymbolAddress((void**)&pACTh, g_acth); cudaGetSymbolAddress((void**)&pACTl, g_actl);
    cudaGetSymbolAddress((void**)&pQKVTh, g_wqkvTh); cudaGetSymbolAddress((void**)&pQKVTl, g_wqkvTl);
    cudaGetSymbolAddress((void**)&pWOTh, g_woTh); cudaGetSymbolAddress((void**)&pWOTl, g_woTl);
    cudaGetSymbolAddress((void**)&pGUTh, g_guTh); cudaGetSymbolAddress((void**)&pGUTl, g_guTl);
    cudaGetSymbolAddress((void**)&pDNTh, g_dnTh); cudaGetSymbolAddress((void**)&pDNTl, g_dnTl);

    cudaFuncSetAttribute(hgemm<false>, cudaFuncAttributeMaxDynamicSharedMemorySize, HG_SMEM);
    cudaFuncSetAttribute(hgemm<true>,  cudaFuncAttributeMaxDynamicSharedMemorySize, HG_SMEM);

    dim3 blk16(16, 16), blkT(32, 8);
    const float inv_sqrt_d = 0.08838834764831843f;

    // weight transpose+convert (bf16 hi/lo, [N,K])
    convT_kernel<<<dim3(QKVW/32,  HIDD/32), blkT>>>(wqkv,      pQKVTh, pQKVTl, HIDD, QKVW);
    convT_kernel<<<dim3(HIDD/32,  HIDD/32), blkT>>>(wo,        pWOTh,  pWOTl,  HIDD, HIDD);
    convT_kernel<<<dim3(2*FFI/32, HIDD/32), blkT>>>(w_gate_up, pGUTh,  pGUTl,  HIDD, 2*FFI);
    convT_kernel<<<dim3(HIDD/32,  FFI/32),  blkT>>>(w_down,    pDNTh,  pDNTl,  FFI,  HIDD);

    // 1. h = rmsnorm(x) -> bf16 hi/lo
    rmsnorm_bf16_kernel<<<(int)BS, 256>>>(x, ln1_w, pHh, pHl);

    // 2. qkv = h @ wqkv  (HMMA)
    hgemm<false><<<dim3((int)(BS/128), QKVW/128), 256, HG_SMEM>>>(
        pHh, pHl, pQKVTh, pQKVTl, nullptr, pQKV, HIDD, QKVW);

    // 3. rope
    rope_kernel<<<dim3((unsigned)BS, NH + NKV), 64>>>(pQKV, pos, S);

    // 4. scores = QK^T / sqrt(D), causal (SIMT)
    gemm128<true, true><<<dim3(S/128, S/128, Bb*NH), blk16>>>(
        pQKV, pQKV + NH*HD, pSC,
        S, S, HD, QKVW, QKVW, S, NH, NH/NKV,
        (long)S*QKVW, HD, (long)S*QKVW, HD, (long)NH*S*S, (long)S*S,
        inv_sqrt_d);

    // 5. softmax
    softmax_kernel<<<(unsigned)(Bb*NH*S), 256>>>(pSC, S);

    // 6. O = P @ V (SIMT) -> [b,s,h,d]
    gemm128<false, false><<<dim3(HD/128, S/128, Bb*NH), blk16>>>(
        pSC, pQKV + (NH+NKV)*HD, pAO,
        S, HD, S, S, QKVW, HIDD, NH, NH/NKV,
        (long)NH*S*S, (long)S*S, (long)S*QKVW, HD, (long)S*HIDD, HD,
        1.f);

    // 6b. convert attnout -> bf16 hi/lo
    conv_hilo_kernel<<<(unsigned)((BS*HIDD + 255)/256), 256>>>(pAO, pAOh, pAOl, BS*HIDD);

    // 7. h1 = x + attnout @ wo  (HMMA, fused residual)
    hgemm<true><<<dim3((int)(BS/128), HIDD/128), 256, HG_SMEM>>>(
        pAOh, pAOl, pWOTh, pWOTl, x, pH1, HIDD, HIDD);

    // 8. h2 = rmsnorm(h1) -> bf16 hi/lo
    rmsnorm_bf16_kernel<<<(int)BS, 256>>>(pH1, ln2_w, pHh, pHl);

    // 9. gu = h2 @ w_gate_up  (HMMA)
    hgemm<false><<<dim3((int)(BS/128), 2*FFI/128), 256, HG_SMEM>>>(
        pHh, pHl, pGUTh, pGUTl, nullptr, pGU, HIDD, 2*FFI);

    // 10. act = silu(gate)*up -> bf16 hi/lo
    long total = BS * FFI;
    silu_bf16_kernel<<<(unsigned)((total + 255)/256), 256>>>(pGU, pACTh, pACTl, total);

    // 11. out = h1 + act @ w_down  (HMMA, fused residual)
    hgemm<true><<<dim3((int)(BS/128), HIDD/128), 256, HG_SMEM>>>(
        pACTh, pACTl, pDNTh, pDNTl, pH1, out, FFI, HIDD);
}